// round 14
// baseline (speedup 1.0000x reference)
#include <cuda_runtime.h>
#include <cuda_bf16.h>

typedef unsigned long long ull;
typedef unsigned int uint;

#define BB 8
#define NP 4096
#define CI 64
#define CO 64
#define KK 20
#define NTILE 32
#define NPAIRS (NTILE * (NTILE + 1) / 2)
#define TSTRIDE 132
#define RSTRIDE 400              // smem row pitch (bytes) for 192 bf16 + pad

// ---------------- scratch ----------------------------------------------------
static __device__ float g_dist[(size_t)BB * NP * NP];
static __device__ float g_tmax[(size_t)BB * NP * NTILE];
static __device__ __nv_bfloat16 g_pl[(size_t)BB * NP * 192]; // 3 bf16 planes/row
static __device__ float g_xx[BB * NP];
static __device__ int   g_idx[BB * NP * KK];
static __device__ float g_a [BB * NP * CO];
static __device__ float g_cc[BB * NP * CO];
static __device__ float g_hmax[(size_t)BB * NP * CO];
static __device__ float g_hmin[(size_t)BB * NP * CO];
static __device__ float g_sum[CO], g_sumsq[CO], g_scale[CO], g_bias[CO];

// ---------------- helpers ----------------------------------------------------
__device__ __forceinline__ void cp16(uint s, const void* g) {
    asm volatile("cp.async.cg.shared.global [%0], [%1], 16;" :: "r"(s), "l"(g));
}
__device__ __forceinline__ void cp_commit() { asm volatile("cp.async.commit_group;"); }
__device__ __forceinline__ void cp_wait0()  { asm volatile("cp.async.wait_group 0;" ::: "memory"); }
__device__ __forceinline__ void ldsm4(uint4& r, uint a) {
    asm volatile("ldmatrix.sync.aligned.m8n8.x4.shared.b16 {%0,%1,%2,%3}, [%4];"
        : "=r"(r.x), "=r"(r.y), "=r"(r.z), "=r"(r.w) : "r"(a));
}
__device__ __forceinline__ void mma16816(float* d, const uint4& a, uint b0, uint b1) {
    asm volatile("mma.sync.aligned.m16n8k16.row.col.f32.bf16.bf16.f32 "
        "{%0,%1,%2,%3}, {%4,%5,%6,%7}, {%8,%9}, {%0,%1,%2,%3};"
        : "+f"(d[0]), "+f"(d[1]), "+f"(d[2]), "+f"(d[3])
        : "r"(a.x), "r"(a.y), "r"(a.z), "r"(a.w), "r"(b0), "r"(b1));
}

// ---------------- 0/1: stats + norms -----------------------------------------
__global__ void zero_stats_k() { int t = threadIdx.x; if (t < CO) { g_sum[t] = 0.f; g_sumsq[t] = 0.f; } }

__global__ void xx_k(const float* __restrict__ x) {
    int g = blockIdx.x * blockDim.x + threadIdx.x;
    int b = g >> 12, n = g & (NP - 1);
    const float* xb = x + (size_t)b * CI * NP + n;
    float s = 0.f;
    #pragma unroll
    for (int c = 0; c < CI; ++c) { float v = xb[c * NP]; s = fmaf(v, v, s); }
    g_xx[g] = s;
}

// ---------------- 2: bf16 plane prep -----------------------------------------
__global__ __launch_bounds__(256) void prep_k(const float* __restrict__ x) {
    __shared__ float sx[64][132];
    int b = blockIdx.y, n0 = blockIdx.x << 7, tid = threadIdx.x;
    for (int i = tid; i < 64 * 32; i += 256) {
        int c = i >> 5, j = (i & 31) << 2;
        *(float4*)&sx[c][j] = *(const float4*)(x + ((size_t)b * CI + c) * NP + n0 + j);
    }
    __syncthreads();
    int n = tid & 127, h = (tid >> 7) * 32;   // this thread: channels h..h+31
    __nv_bfloat16* row = g_pl + ((size_t)b * NP + n0 + n) * 192;
    uint u0[16], u1[16], u2[16];
    #pragma unroll
    for (int q = 0; q < 32; ++q) {
        float v = sx[h + q][n];
        __nv_bfloat16 h0 = __float2bfloat16(v);
        float r1 = v - __bfloat162float(h0);
        __nv_bfloat16 h1 = __float2bfloat16(r1);
        __nv_bfloat16 h2 = __float2bfloat16(r1 - __bfloat162float(h1));
        uint s0 = (uint)__bfloat16_as_ushort(h0);
        uint s1 = (uint)__bfloat16_as_ushort(h1);
        uint s2 = (uint)__bfloat16_as_ushort(h2);
        int w = q >> 1;
        if (!(q & 1)) { u0[w] = s0; u1[w] = s1; u2[w] = s2; }
        else { u0[w] |= s0 << 16; u1[w] |= s1 << 16; u2[w] |= s2 << 16; }
    }
    #pragma unroll
    for (int k = 0; k < 4; ++k) {
        *(uint4*)(row + 0   + h + k * 8) = make_uint4(u0[k*4], u0[k*4+1], u0[k*4+2], u0[k*4+3]);
        *(uint4*)(row + 64  + h + k * 8) = make_uint4(u1[k*4], u1[k*4+1], u1[k*4+2], u1[k*4+3]);
        *(uint4*)(row + 128 + h + k * 8) = make_uint4(u2[k*4], u2[k*4+1], u2[k*4+2], u2[k*4+3]);
    }
}

// ---------------- 3: ac_k (unchanged) ----------------------------------------
__global__ __launch_bounds__(256) void ac_k(const float* __restrict__ x, const float* __restrict__ W) {
    __shared__ float sWd[CI * CO], sW2[CI * CO];
    int tid = threadIdx.x;
    for (int i = tid; i < CI * CO; i += 256) {
        int o = i >> 6, c = i & 63;
        float w1 = W[o * 128 + c], w2 = W[o * 128 + 64 + c];
        sWd[c * CO + o] = w1 - w2; sW2[c * CO + o] = w2;
    }
    __syncthreads();
    int b = blockIdx.y, n = blockIdx.x * 128 + (tid & 127), o0 = (tid >> 7) * 32;
    float aa[32], cc[32];
    #pragma unroll
    for (int j = 0; j < 32; ++j) { aa[j] = 0.f; cc[j] = 0.f; }
    const float* xb = x + (size_t)b * CI * NP + n;
    for (int c = 0; c < CI; ++c) {
        float xv = xb[c * NP];
        const float4* wd4 = (const float4*)(sWd + c * CO + o0);
        const float4* w24 = (const float4*)(sW2 + c * CO + o0);
        #pragma unroll
        for (int j4 = 0; j4 < 8; ++j4) {
            float4 wd = wd4[j4], w2 = w24[j4];
            aa[j4*4+0] = fmaf(xv, wd.x, aa[j4*4+0]); aa[j4*4+1] = fmaf(xv, wd.y, aa[j4*4+1]);
            aa[j4*4+2] = fmaf(xv, wd.z, aa[j4*4+2]); aa[j4*4+3] = fmaf(xv, wd.w, aa[j4*4+3]);
            cc[j4*4+0] = fmaf(xv, w2.x, cc[j4*4+0]); cc[j4*4+1] = fmaf(xv, w2.y, cc[j4*4+1]);
            cc[j4*4+2] = fmaf(xv, w2.z, cc[j4*4+2]); cc[j4*4+3] = fmaf(xv, w2.w, cc[j4*4+3]);
        }
    }
    size_t base = ((size_t)b * NP + n) * CO + o0;
    #pragma unroll
    for (int j = 0; j < 32; ++j) { g_a[base + j] = aa[j]; g_cc[base + j] = cc[j]; }
}

// ---------------- 4: HMMA Gram (triangular pairs) ----------------------------
#define GH_SMEM (2 * 128 * RSTRIDE)   // 102400 B; transposed stage overlaps

__global__ __launch_bounds__(256, 2) void gram_h() {
    extern __shared__ char smraw[];
    const uint sA = (uint)__cvta_generic_to_shared(smraw);
    const uint sB = sA + 128 * RSTRIDE;
    float* sT = (float*)smraw;            // reused after mainloop
    const int tid = threadIdx.x, wid = tid >> 5, lane = tid & 31;
    const int b = blockIdx.y;
    int p = blockIdx.x;
    int tj = (int)((sqrtf(8.f * p + 1.f) - 1.f) * 0.5f);
    while ((tj + 1) * (tj + 2) / 2 <= p) ++tj;
    while (tj * (tj + 1) / 2 > p) --tj;
    int ti = p - tj * (tj + 1) / 2;
    const int n0 = ti << 7, m0 = tj << 7;
    const float* xxg = g_xx + b * NP;

    // load both plane tiles (24 x 16B per row)
    for (int i = tid; i < 2 * 128 * 24; i += 256) {
        int t = i >= 3072;
        int r = (i - t * 3072) / 24, j = (i - t * 3072) % 24;
        const char* src = (const char*)(g_pl + ((size_t)b * NP + (t ? m0 : n0) + r) * 192) + j * 16;
        cp16((t ? sB : sA) + (uint)(r * RSTRIDE + j * 16), src);
    }
    cp_commit(); cp_wait0(); __syncthreads();

    float C[16][4];
    #pragma unroll
    for (int f = 0; f < 16; ++f)
        #pragma unroll
        for (int q = 0; q < 4; ++q) C[f][q] = 0.f;

    const uint aBase = sA + (uint)((wid * 16 + (lane & 15)) * RSTRIDE + (lane >> 4) * 16);
    const uint bRow  = (lane & 7) + ((lane >> 4) << 3);
    const uint bBase = sB + (uint)(bRow * RSTRIDE + ((lane >> 3) & 1) * 16);
    const int AIDX[6] = {0, 0, 1, 1, 0, 2};
    const int BIDX[6] = {0, 1, 0, 1, 2, 0};

    #pragma unroll
    for (int kb = 0; kb < 6; ++kb) {
        uint ak = (uint)(AIDX[kb] * 128), bk = (uint)(BIDX[kb] * 128);
        #pragma unroll
        for (int s = 0; s < 4; ++s) {
            uint4 af; ldsm4(af, aBase + ak + s * 32);
            #pragma unroll
            for (int mf = 0; mf < 8; ++mf) {
                uint4 bf; ldsm4(bf, bBase + (uint)(mf * 16 * RSTRIDE) + bk + s * 32);
                mma16816(C[mf * 2],     af, bf.x, bf.y);
                mma16816(C[mf * 2 + 1], af, bf.z, bf.w);
            }
        }
    }

    // direct epilogue: rows n0-strip, cols m0-strip
    int r0 = wid * 16 + (lane >> 2);
    int cb = (lane & 3) * 2;
    float mx0 = -3.4e38f, mx1 = -3.4e38f;
    #pragma unroll
    for (int f = 0; f < 16; ++f) {
        int mc = m0 + f * 8 + cb;
        float2 w = *(const float2*)(xxg + mc);
        float2 v0, v1;
        v0.x = fmaf(-0.5f, w.x, C[f][0]); v0.y = fmaf(-0.5f, w.y, C[f][1]);
        v1.x = fmaf(-0.5f, w.x, C[f][2]); v1.y = fmaf(-0.5f, w.y, C[f][3]);
        *(float2*)(g_dist + ((size_t)b * NP + n0 + r0) * NP + mc)     = v0;
        *(float2*)(g_dist + ((size_t)b * NP + n0 + r0 + 8) * NP + mc) = v1;
        mx0 = fmaxf(mx0, fmaxf(v0.x, v0.y));
        mx1 = fmaxf(mx1, fmaxf(v1.x, v1.y));
    }
    #pragma unroll
    for (int o = 1; o <= 2; o <<= 1) {
        mx0 = fmaxf(mx0, __shfl_xor_sync(0xffffffffu, mx0, o));
        mx1 = fmaxf(mx1, __shfl_xor_sync(0xffffffffu, mx1, o));
    }
    if ((lane & 3) == 0) {
        g_tmax[((size_t)b * NP + n0 + r0) * NTILE + tj]     = mx0;
        g_tmax[((size_t)b * NP + n0 + r0 + 8) * NTILE + tj] = mx1;
    }

    // transposed orientation (off-diagonal): stage raw scores, drain coalesced
    if (ti != tj) {
        __syncthreads();          // operand smem now reusable
        #pragma unroll
        for (int f = 0; f < 16; ++f) {
            int c = f * 8 + cb;
            sT[c * TSTRIDE + r0]           = C[f][0];
            sT[(c + 1) * TSTRIDE + r0]     = C[f][1];
            sT[c * TSTRIDE + r0 + 8]       = C[f][2];
            sT[(c + 1) * TSTRIDE + r0 + 8] = C[f][3];
        }
        __syncthreads();
        int r = tid >> 1, h = tid & 1;
        const float* rowT = sT + r * TSTRIDE;
        float rmax = -3.4e38f;
        size_t gb = ((size_t)b * NP + m0 + r) * NP + n0;
        #pragma unroll
        for (int k = 0; k < 16; ++k) {
            int col = (k << 3) + (h << 2);
            float4 v = *(const float4*)(rowT + col);
            float4 xv = *(const float4*)(xxg + n0 + col);
            v.x = fmaf(-0.5f, xv.x, v.x); v.y = fmaf(-0.5f, xv.y, v.y);
            v.z = fmaf(-0.5f, xv.z, v.z); v.w = fmaf(-0.5f, xv.w, v.w);
            *(float4*)(g_dist + gb + col) = v;
            rmax = fmaxf(rmax, fmaxf(fmaxf(v.x, v.y), fmaxf(v.z, v.w)));
        }
        rmax = fmaxf(rmax, __shfl_xor_sync(0xffffffffu, rmax, 1));
        if (h == 0) g_tmax[((size_t)b * NP + m0 + r) * NTILE + ti] = rmax;
    }
}

// ---------------- 5: pruned top-20 select ------------------------------------
__global__ __launch_bounds__(256) void select2_k() {
    const int row = (blockIdx.x * 256 + threadIdx.x) >> 5;
    const int lane = threadIdx.x & 31;
    const float NEG = __int_as_float(0xff800000);
    const unsigned FULL = 0xffffffffu;
    float tmv = g_tmax[(size_t)row * NTILE + lane];
    float thr0;
    {
        float s = tmv;
        #pragma unroll
        for (int k = 2; k <= 32; k <<= 1)
            #pragma unroll
            for (int j = k >> 1; j; j >>= 1) {
                float tt = __shfl_xor_sync(FULL, s, j);
                bool asc = ((lane & k) == 0), lower = ((lane & j) == 0);
                float mn = fminf(s, tt), mx = fmaxf(s, tt);
                s = (asc == lower) ? mn : mx;
            }
        thr0 = __shfl_sync(FULL, s, 12);
    }
    float lv = NEG; int li = 0; float thr = NEG;
    const float* base = g_dist + (size_t)row * NP;
    for (int it = 0; it < NTILE; ++it) {
        float bv = tmv; int bt = lane;
        #pragma unroll
        for (int off = 16; off; off >>= 1) {
            float ov = __shfl_xor_sync(FULL, bv, off);
            int ot = __shfl_xor_sync(FULL, bt, off);
            if (ov > bv || (ov == bv && ot < bt)) { bv = ov; bt = ot; }
        }
        if (bv < thr0 || bv <= thr) break;
        if (lane == bt) tmv = NEG;
        float4 v4 = *(const float4*)(base + (bt << 7) + (lane << 2));
        int ib = (bt << 7) + (lane << 2);
        #pragma unroll
        for (int e = 0; e < 4; ++e) {
            float v = (e == 0) ? v4.x : (e == 1) ? v4.y : (e == 2) ? v4.z : v4.w;
            bool pend = (v >= thr0) && (v > thr);
            while (true) {
                unsigned ball = __ballot_sync(FULL, pend);
                if (!ball) break;
                int src = __ffs(ball) - 1;
                float cv = __shfl_sync(FULL, v, src);
                int ci = __shfl_sync(FULL, ib + e, src);
                unsigned gb = __ballot_sync(FULL, lane < KK && lv >= cv);
                int pos = __popc(gb);
                float sv = __shfl_up_sync(FULL, lv, 1);
                int si = __shfl_up_sync(FULL, li, 1);
                if (lane > pos) { lv = sv; li = si; }
                else if (lane == pos) { lv = cv; li = ci; }
                thr = __shfl_sync(FULL, lv, KK - 1);
                if (lane == src) pend = false;
                pend = pend && (v > thr);
            }
        }
    }
    if (lane < KK) g_idx[(size_t)row * KK + lane] = li;
}

// ---------------- 6/7/8: tail ------------------------------------------------
__global__ __launch_bounds__(256) void maxmin_k() {
    __shared__ float sSum[CO], sSq[CO];
    int tid = threadIdx.x;
    if (tid < CO) { sSum[tid] = 0.f; sSq[tid] = 0.f; }
    __syncthreads();
    int o = tid & 63, r = blockIdx.x * 4 + (tid >> 6), b = r >> 12;
    float av = g_a[(size_t)r * CO + o];
    const int* ip = g_idx + (size_t)r * KK;
    const float PINF = __int_as_float(0x7f800000);
    float mx = -PINF, mn = PINF, s = 0.f, s2 = 0.f;
    #pragma unroll
    for (int k = 0; k < KK; ++k) {
        int j = ip[k];
        float e = av + g_cc[((size_t)(b << 12) + j) * CO + o];
        mx = fmaxf(mx, e); mn = fminf(mn, e);
        s += e; s2 = fmaf(e, e, s2);
    }
    g_hmax[(size_t)r * CO + o] = mx;
    g_hmin[(size_t)r * CO + o] = mn;
    atomicAdd(&sSum[o], s); atomicAdd(&sSq[o], s2);
    __syncthreads();
    if (tid < CO) { atomicAdd(&g_sum[tid], sSum[tid]); atomicAdd(&g_sumsq[tid], sSq[tid]); }
}

__global__ void finalize_k(const float* __restrict__ gamma, const float* __restrict__ beta) {
    int o = threadIdx.x;
    const float cnt = (float)BB * NP * KK;
    float mean = g_sum[o] / cnt;
    float var = g_sumsq[o] / cnt - mean * mean;
    float sc = gamma[o] * rsqrtf(var + 1e-5f);
    g_scale[o] = sc; g_bias[o] = fmaf(-mean, sc, beta[o]);
}

__global__ __launch_bounds__(256) void out_k(float* __restrict__ out) {
    __shared__ float sm[64][65];
    int tid = threadIdx.x, b = blockIdx.y, n0 = blockIdx.x * 64;
    #pragma unroll
    for (int it = 0; it < 16; ++it) {
        int i = it * 4 + (tid >> 6), o = tid & 63;
        float sc = g_scale[o];
        size_t idx = ((size_t)b * NP + n0 + i) * CO + o;
        float h = (sc >= 0.f) ? g_hmax[idx] : g_hmin[idx];
        float v = fmaf(sc, h, g_bias[o]);
        sm[i][o] = (v >= 0.f) ? v : 0.2f * v;
    }
    __syncthreads();
    #pragma unroll
    for (int it = 0; it < 16; ++it) {
        int o = it * 4 + (tid >> 6), n = tid & 63;
        out[((size_t)b * CO + o) * NP + n0 + n] = sm[n][o];
    }
}

// ---------------- launch ------------------------------------------------------
extern "C" void kernel_launch(void* const* d_in, const int* in_sizes, int n_in,
                              void* d_out, int out_size) {
    const float* x = (const float*)d_in[0];
    const float* W = (const float*)d_in[1];
    const float* gamma = (const float*)d_in[2];
    const float* beta = (const float*)d_in[3];
    float* out = (float*)d_out;

    cudaFuncSetAttribute(gram_h, cudaFuncAttributeMaxDynamicSharedMemorySize, GH_SMEM);

    zero_stats_k<<<1, 64>>>();
    xx_k<<<(BB * NP) / 256, 256>>>(x);
    prep_k<<<dim3(NP / 128, BB), 256>>>(x);
    ac_k<<<dim3(NP / 128, BB), 256>>>(x, W);
    gram_h<<<dim3(NPAIRS, BB), 256, GH_SMEM>>>();
    select2_k<<<(BB * NP) / 8, 256>>>();
    maxmin_k<<<(BB * NP) / 4, 256>>>();
    finalize_k<<<1, 64>>>(gamma, beta);
    out_k<<<dim3(NP / 64, BB), 256>>>(out);
}

// round 15
// speedup vs baseline: 1.4728x; 1.4728x over previous
#include <cuda_runtime.h>

typedef unsigned long long ull;
typedef unsigned int uint;

#define BB   8
#define NP   4096
#define CI   64
#define CO   64
#define KK   20
#define NTILE 32
#define NPAIRS (NTILE * (NTILE + 1) / 2)   // 528
#define TSTRIDE 132

// ---------------- scratch ----------------------------------------------------
static __device__ float g_dist[(size_t)BB * NP * NP];
static __device__ float g_tmax[(size_t)BB * NP * NTILE];
static __device__ float g_xx[BB * NP];
static __device__ int   g_idx[BB * NP * KK];
static __device__ float g_a [BB * NP * CO];
static __device__ float g_cc[BB * NP * CO];
static __device__ float g_hmax[(size_t)BB * NP * CO];
static __device__ float g_hmin[(size_t)BB * NP * CO];
static __device__ float g_sum[CO], g_sumsq[CO], g_scale[CO], g_bias[CO];

// ---------------- helpers ----------------------------------------------------
__device__ __forceinline__ ull ffma2(ull a, ull b, ull c) {
    ull d;
    asm("fma.rn.f32x2 %0, %1, %2, %3;" : "=l"(d) : "l"(a), "l"(b), "l"(c));
    return d;
}
__device__ __forceinline__ ull dup2(float f) {
    unsigned u = __float_as_uint(f);
    return (ull)u | ((ull)u << 32);
}
__device__ __forceinline__ float acc_lo(ull a) { return __uint_as_float((unsigned)a); }
__device__ __forceinline__ float acc_hi(ull a) { return __uint_as_float((unsigned)(a >> 32)); }
__device__ __forceinline__ void cp16(uint s, const void* g) {
    asm volatile("cp.async.cg.shared.global [%0], [%1], 16;" :: "r"(s), "l"(g));
}
__device__ __forceinline__ void cp_commit() { asm volatile("cp.async.commit_group;"); }
__device__ __forceinline__ void cp_wait0()  { asm volatile("cp.async.wait_group 0;" ::: "memory"); }

// ---------------- 0: zero channel stats --------------------------------------
__global__ void zero_stats_k() {
    int t = threadIdx.x;
    if (t < CO) { g_sum[t] = 0.f; g_sumsq[t] = 0.f; }
}

// ---------------- 1: squared norms -------------------------------------------
__global__ void xx_k(const float* __restrict__ x) {
    int g = blockIdx.x * blockDim.x + threadIdx.x;
    int b = g >> 12, n = g & (NP - 1);
    const float* xb = x + (size_t)b * CI * NP + n;
    float s = 0.f;
    #pragma unroll
    for (int c = 0; c < CI; ++c) { float v = xb[c * NP]; s = fmaf(v, v, s); }
    g_xx[g] = s;
}

// ---------------- 2: a = (W1-W2)@x_n, c = W2@x_n  (4-way o-split) ------------
__global__ __launch_bounds__(256) void ac_k(const float* __restrict__ x,
                                            const float* __restrict__ W) {
    __shared__ float sWd[CI * CO], sW2[CI * CO];   // [c][o]
    int tid = threadIdx.x;
    for (int i = tid; i < CI * CO; i += 256) {
        int o = i >> 6, c = i & 63;
        float w1 = W[o * 128 + c], w2 = W[o * 128 + 64 + c];
        sWd[c * CO + o] = w1 - w2; sW2[c * CO + o] = w2;
    }
    __syncthreads();
    int b  = blockIdx.y;
    int n  = blockIdx.x * 64 + (tid & 63);
    int o0 = (tid >> 6) * 16;                      // 4 o-groups of 16
    float aa[16], cc[16];
    #pragma unroll
    for (int j = 0; j < 16; ++j) { aa[j] = 0.f; cc[j] = 0.f; }
    const float* xb = x + (size_t)b * CI * NP + n;
    #pragma unroll 4
    for (int c = 0; c < CI; ++c) {
        float xv = xb[(size_t)c * NP];
        const float4* wd4 = (const float4*)(sWd + c * CO + o0);
        const float4* w24 = (const float4*)(sW2 + c * CO + o0);
        #pragma unroll
        for (int j4 = 0; j4 < 4; ++j4) {
            float4 wd = wd4[j4], w2 = w24[j4];
            aa[j4*4+0] = fmaf(xv, wd.x, aa[j4*4+0]);
            aa[j4*4+1] = fmaf(xv, wd.y, aa[j4*4+1]);
            aa[j4*4+2] = fmaf(xv, wd.z, aa[j4*4+2]);
            aa[j4*4+3] = fmaf(xv, wd.w, aa[j4*4+3]);
            cc[j4*4+0] = fmaf(xv, w2.x, cc[j4*4+0]);
            cc[j4*4+1] = fmaf(xv, w2.y, cc[j4*4+1]);
            cc[j4*4+2] = fmaf(xv, w2.z, cc[j4*4+2]);
            cc[j4*4+3] = fmaf(xv, w2.w, cc[j4*4+3]);
        }
    }
    float* pa = g_a  + ((size_t)b * NP + n) * CO + o0;
    float* pc = g_cc + ((size_t)b * NP + n) * CO + o0;
    #pragma unroll
    for (int j4 = 0; j4 < 4; ++j4) {
        *(float4*)(pa + j4 * 4) = make_float4(aa[j4*4], aa[j4*4+1], aa[j4*4+2], aa[j4*4+3]);
        *(float4*)(pc + j4 * 4) = make_float4(cc[j4*4], cc[j4*4+1], cc[j4*4+2], cc[j4*4+3]);
    }
}

// ---------------- 3: Gram (triangular tile pairs) + per-(row,tile) max -------
#define GS_TOTAL (128 * TSTRIDE * 4)    // 67,584 B (>= sQ 32KB + sP 32KB)

__global__ __launch_bounds__(256, 2) void gram_k(const float* __restrict__ x) {
    extern __shared__ char smraw[];
    float* sQ = (float*)smraw;              // [c][128] rows-tile (ti)
    float* sP = sQ + 64 * 128;              // [c][128] cols-tile (tj)
    const int tid = threadIdx.x;
    const int b   = blockIdx.y;
    int p  = blockIdx.x;
    int tj = (int)((sqrtf(8.f * p + 1.f) - 1.f) * 0.5f);
    while ((tj + 1) * (tj + 2) / 2 <= p) ++tj;
    while (tj * (tj + 1) / 2 > p) --tj;
    int ti = p - tj * (tj + 1) / 2;
    const int n0 = ti << 7;
    const int m0 = tj << 7;
    const float* xb = x + (size_t)b * CI * NP;

    {
        uint sq = (uint)__cvta_generic_to_shared(sQ);
        uint sp = (uint)__cvta_generic_to_shared(sP);
        #pragma unroll
        for (int k = 0; k < 8; ++k) {
            int i = k * 256 + tid;
            int c = i >> 5, j = (i & 31) << 2;
            uint off = (uint)(c * 128 + j) * 4;
            cp16(sq + off, xb + (size_t)c * NP + n0 + j);
            cp16(sp + off, xb + (size_t)c * NP + m0 + j);
        }
        cp_commit();
    }

    const int tx = tid & 15;      // m-pair: pr = tx + 16*g  ->  m = 2pr, 2pr+1
    const int ty = tid >> 4;      // n: row = ty*8 + i
    const float* xxg = g_xx + b * NP;

    ull acc[8][4];
    #pragma unroll
    for (int i = 0; i < 8; ++i)
        #pragma unroll
        for (int g = 0; g < 4; ++g) acc[i][g] = 0ull;

    cp_wait0();
    __syncthreads();

    #pragma unroll 4
    for (int c = 0; c < CI; ++c) {
        const float* qp = sQ + c * 128 + ty * 8;
        float4 qa = *(const float4*)qp;          // LDS.128 broadcast per ty
        float4 qb = *(const float4*)(qp + 4);
        ull q[8];
        q[0] = dup2(qa.x); q[1] = dup2(qa.y); q[2] = dup2(qa.z); q[3] = dup2(qa.w);
        q[4] = dup2(qb.x); q[5] = dup2(qb.y); q[6] = dup2(qb.z); q[7] = dup2(qb.w);
        ull pp[4];
        const ull* pr = (const ull*)(sP + c * 128);
        #pragma unroll
        for (int g = 0; g < 4; ++g) pp[g] = pr[tx + (g << 4)];
        #pragma unroll
        for (int i = 0; i < 8; ++i)
            #pragma unroll
            for (int g = 0; g < 4; ++g) acc[i][g] = ffma2(q[i], pp[g], acc[i][g]);
    }

    // ---- direct orientation ----
    size_t rb = (size_t)b * NP + n0 + ty * 8;
    float2 wng[4];
    #pragma unroll
    for (int g = 0; g < 4; ++g) {
        float2 w = *(const float2*)(xxg + m0 + ((tx + (g << 4)) << 1));
        wng[g].x = -0.5f * w.x; wng[g].y = -0.5f * w.y;
    }
    #pragma unroll
    for (int i = 0; i < 8; ++i) {
        float rmax = __int_as_float(0xff800000);
        #pragma unroll
        for (int g = 0; g < 4; ++g) {
            int mp = tx + (g << 4);
            float2 v;
            v.x = acc_lo(acc[i][g]) + wng[g].x;
            v.y = acc_hi(acc[i][g]) + wng[g].y;
            *(float2*)(g_dist + (rb + i) * NP + m0 + (mp << 1)) = v;
            rmax = fmaxf(rmax, fmaxf(v.x, v.y));
        }
        #pragma unroll
        for (int off = 8; off; off >>= 1)
            rmax = fmaxf(rmax, __shfl_xor_sync(0xffffffffu, rmax, off));
        if (tx == 0) g_tmax[(rb + i) * NTILE + tj] = rmax;
    }

    // ---- transposed orientation (off-diagonal only) ----
    if (ti != tj) {
        __syncthreads();
        float* sT = sQ;                        // [m][n], stride TSTRIDE
        #pragma unroll
        for (int i = 0; i < 8; ++i) {
            int nloc = ty * 8 + i;
            #pragma unroll
            for (int g = 0; g < 4; ++g) {
                int mloc = (tx + (g << 4)) << 1;
                sT[mloc * TSTRIDE + nloc]       = acc_lo(acc[i][g]);
                sT[(mloc + 1) * TSTRIDE + nloc] = acc_hi(acc[i][g]);
            }
        }
        __syncthreads();
        int r = tid >> 1, h = tid & 1;
        const float* rowT = sT + r * TSTRIDE;
        float rmax = __int_as_float(0xff800000);
        size_t gb = ((size_t)b * NP + m0 + r) * NP + n0;
        #pragma unroll
        for (int k = 0; k < 16; ++k) {
            int col = (k << 3) + (h << 2);
            float4 v = *(const float4*)(rowT + col);
            float4 xv = *(const float4*)(xxg + n0 + col);
            v.x = fmaf(-0.5f, xv.x, v.x);
            v.y = fmaf(-0.5f, xv.y, v.y);
            v.z = fmaf(-0.5f, xv.z, v.z);
            v.w = fmaf(-0.5f, xv.w, v.w);
            *(float4*)(g_dist + gb + col) = v;
            rmax = fmaxf(rmax, fmaxf(fmaxf(v.x, v.y), fmaxf(v.z, v.w)));
        }
        rmax = fmaxf(rmax, __shfl_xor_sync(0xffffffffu, rmax, 1));
        if (h == 0) g_tmax[((size_t)b * NP + m0 + r) * NTILE + ti] = rmax;
    }
}

// ---------------- 4: pruned top-20 select (threshold-seeded) -----------------
__global__ __launch_bounds__(256) void select2_k() {
    const int row  = (blockIdx.x * 256 + threadIdx.x) >> 5;
    const int lane = threadIdx.x & 31;
    const float NEG = __int_as_float(0xff800000);
    const unsigned FULL = 0xffffffffu;

    float tmv = g_tmax[(size_t)row * NTILE + lane];
    float thr0;
    {
        float s = tmv;
        #pragma unroll
        for (int k = 2; k <= 32; k <<= 1)
            #pragma unroll
            for (int j = k >> 1; j; j >>= 1) {
                float t = __shfl_xor_sync(FULL, s, j);
                bool asc   = ((lane & k) == 0);
                bool lower = ((lane & j) == 0);
                float mn = fminf(s, t), mx = fmaxf(s, t);
                s = (asc == lower) ? mn : mx;
            }
        thr0 = __shfl_sync(FULL, s, 12);
    }

    float lv = NEG; int li = 0;
    float thr = NEG;
    const float* base = g_dist + (size_t)row * NP;

    for (int it = 0; it < NTILE; ++it) {
        float bv = tmv; int bt = lane;
        #pragma unroll
        for (int off = 16; off; off >>= 1) {
            float ov = __shfl_xor_sync(FULL, bv, off);
            int   ot = __shfl_xor_sync(FULL, bt, off);
            if (ov > bv || (ov == bv && ot < bt)) { bv = ov; bt = ot; }
        }
        if (bv < thr0 || bv <= thr) break;
        if (lane == bt) tmv = NEG;

        float4 v4 = *(const float4*)(base + (bt << 7) + (lane << 2));
        int ib = (bt << 7) + (lane << 2);
        #pragma unroll
        for (int e = 0; e < 4; ++e) {
            float v = (e == 0) ? v4.x : (e == 1) ? v4.y : (e == 2) ? v4.z : v4.w;
            bool pend = (v >= thr0) && (v > thr);
            while (true) {
                unsigned ball = __ballot_sync(FULL, pend);
                if (!ball) break;
                int   src = __ffs(ball) - 1;
                float cv  = __shfl_sync(FULL, v, src);
                int   ci  = __shfl_sync(FULL, ib + e, src);
                unsigned gb = __ballot_sync(FULL, lane < KK && lv >= cv);
                int pos = __popc(gb);
                float sv = __shfl_up_sync(FULL, lv, 1);
                int   si = __shfl_up_sync(FULL, li, 1);
                if (lane > pos)       { lv = sv; li = si; }
                else if (lane == pos) { lv = cv; li = ci; }
                thr = __shfl_sync(FULL, lv, KK - 1);
                if (lane == src) pend = false;
                pend = pend && (v > thr);
            }
        }
    }
    if (lane < KK) g_idx[(size_t)row * KK + lane] = li;
}

// ---------------- 5: per-(b,n,o) max/min over k + channel stats --------------
__global__ __launch_bounds__(256) void maxmin_k() {
    __shared__ float sSum[CO], sSq[CO];
    int tid = threadIdx.x;
    if (tid < CO) { sSum[tid] = 0.f; sSq[tid] = 0.f; }
    __syncthreads();
    int o = tid & 63;
    int r = blockIdx.x * 4 + (tid >> 6);
    int b = r >> 12;
    float av = g_a[(size_t)r * CO + o];
    const int* ip = g_idx + (size_t)r * KK;
    const float PINF = __int_as_float(0x7f800000);
    float mx = -PINF, mn = PINF, s = 0.f, s2 = 0.f;
    #pragma unroll
    for (int k = 0; k < KK; ++k) {
        int j = ip[k];
        float e = av + g_cc[((size_t)(b << 12) + j) * CO + o];
        mx = fmaxf(mx, e); mn = fminf(mn, e);
        s += e; s2 = fmaf(e, e, s2);
    }
    g_hmax[(size_t)r * CO + o] = mx;
    g_hmin[(size_t)r * CO + o] = mn;
    atomicAdd(&sSum[o], s);
    atomicAdd(&sSq[o], s2);
    __syncthreads();
    if (tid < CO) {
        atomicAdd(&g_sum[tid], sSum[tid]);
        atomicAdd(&g_sumsq[tid], sSq[tid]);
    }
}

// ---------------- 6: finalize batchnorm affine -------------------------------
__global__ void finalize_k(const float* __restrict__ gamma,
                           const float* __restrict__ beta) {
    int o = threadIdx.x;
    const float cnt = (float)BB * NP * KK;
    float mean = g_sum[o] / cnt;
    float var  = g_sumsq[o] / cnt - mean * mean;
    float sc   = gamma[o] * rsqrtf(var + 1e-5f);
    g_scale[o] = sc;
    g_bias[o]  = fmaf(-mean, sc, beta[o]);
}

// ---------------- 7: output --------------------------------------------------
__global__ __launch_bounds__(256) void out_k(float* __restrict__ out) {
    __shared__ float sm[64][65];
    int tid = threadIdx.x;
    int b = blockIdx.y, n0 = blockIdx.x * 64;
    #pragma unroll
    for (int it = 0; it < 16; ++it) {
        int i = it * 4 + (tid >> 6), o = tid & 63;
        float sc = g_scale[o];
        size_t idx = ((size_t)b * NP + n0 + i) * CO + o;
        float h = (sc >= 0.f) ? g_hmax[idx] : g_hmin[idx];
        float v = fmaf(sc, h, g_bias[o]);
        sm[i][o] = (v >= 0.f) ? v : 0.2f * v;
    }
    __syncthreads();
    #pragma unroll
    for (int it = 0; it < 16; ++it) {
        int o = it * 4 + (tid >> 6), n = tid & 63;
        out[((size_t)b * CO + o) * NP + n0 + n] = sm[n][o];
    }
}

// ---------------- launch ------------------------------------------------------
extern "C" void kernel_launch(void* const* d_in, const int* in_sizes, int n_in,
                              void* d_out, int out_size) {
    const float* x     = (const float*)d_in[0];
    const float* W     = (const float*)d_in[1];
    const float* gamma = (const float*)d_in[2];
    const float* beta  = (const float*)d_in[3];
    float* out = (float*)d_out;

    cudaFuncSetAttribute(gram_k, cudaFuncAttributeMaxDynamicSharedMemorySize,
                         GS_TOTAL);

    zero_stats_k<<<1, 64>>>();
    xx_k<<<(BB * NP) / 256, 256>>>(x);
    ac_k<<<dim3(NP / 64, BB), 256>>>(x, W);
    gram_k<<<dim3(NPAIRS, BB), 256, GS_TOTAL>>>(x);
    select2_k<<<(BB * NP) / 8, 256>>>();
    maxmin_k<<<(BB * NP) / 4, 256>>>();
    finalize_k<<<1, 64>>>(gamma, beta);
    out_k<<<dim3(NP / 64, BB), 256>>>(out);
}